// round 1
// baseline (speedup 1.0000x reference)
#include <cuda_runtime.h>

#define S_LEN  4096
#define BATCH  2
#define NH     12
#define HD     64
#define E_DIM  768
#define QKV_N  2304
#define NTOK   (BATCH * S_LEN)

// Scratch (allocation-free rule: __device__ globals)
__device__ float g_Q[(size_t)BATCH * NH * S_LEN * HD];   // 24 MB, pre-scaled by 0.125
__device__ float g_K[(size_t)BATCH * NH * S_LEN * HD];
__device__ float g_V[(size_t)BATCH * NH * S_LEN * HD];
__device__ float g_Att[(size_t)NTOK * E_DIM];            // attended, [B*S, E]

// ---------------------------------------------------------------------------
// Kernel 1: QKV projection.  C[N=8192, 2304] = X @ W + b, scattered to Q/K/V
// [B,H,S,D] layouts. 64x64 tile, BK=16, 4x4 per-thread microtile, 256 threads.
// ---------------------------------------------------------------------------
__global__ __launch_bounds__(256) void qkv_gemm(
    const float* __restrict__ x, const float* __restrict__ w,
    const float* __restrict__ bias)
{
    __shared__ float As[64][17];   // pad -> no bank conflicts on As[row][k]
    __shared__ float Bs[16][64];

    const int t  = threadIdx.x;
    const int tx = t & 15, ty = t >> 4;
    const int row0 = blockIdx.y * 64;
    const int col0 = blockIdx.x * 64;

    float acc[4][4] = {};

    for (int kk = 0; kk < E_DIM; kk += 16) {
#pragma unroll
        for (int i = 0; i < 4; i++) {
            int idx = t + i * 256;
            int r = idx >> 4, c = idx & 15;
            As[r][c] = x[(size_t)(row0 + r) * E_DIM + kk + c];
        }
#pragma unroll
        for (int i = 0; i < 4; i++) {
            int idx = t + i * 256;
            int r = idx >> 6, c = idx & 63;
            Bs[r][c] = w[(size_t)(kk + r) * QKV_N + col0 + c];
        }
        __syncthreads();
#pragma unroll
        for (int k = 0; k < 16; k++) {
            float a[4], bv[4];
#pragma unroll
            for (int i = 0; i < 4; i++) a[i] = As[ty * 4 + i][k];
#pragma unroll
            for (int j = 0; j < 4; j++) bv[j] = Bs[k][tx * 4 + j];
#pragma unroll
            for (int i = 0; i < 4; i++)
#pragma unroll
                for (int j = 0; j < 4; j++)
                    acc[i][j] += a[i] * bv[j];
        }
        __syncthreads();
    }

#pragma unroll
    for (int i = 0; i < 4; i++) {
        int m = row0 + ty * 4 + i;
        int b = m >> 12;          // / 4096
        int s = m & 4095;
#pragma unroll
        for (int j = 0; j < 4; j++) {
            int c = col0 + tx * 4 + j;
            float v = acc[i][j] + bias[c];
            int part = c / E_DIM;
            int h = (c % E_DIM) >> 6;
            int d = c & 63;
            size_t idx = ((size_t)(b * NH + h) * S_LEN + s) * HD + d;
            if (part == 0)      g_Q[idx] = v * 0.125f;   // fold 1/sqrt(64)
            else if (part == 1) g_K[idx] = v;
            else                g_V[idx] = v;
        }
    }
}

// ---------------------------------------------------------------------------
// Kernel 2: causal flash attention, fp32, online softmax.
// grid = (S/64, H, B), 256 threads. BM=BN=64, D=64.
// ---------------------------------------------------------------------------
__global__ __launch_bounds__(256) void attn_kernel()
{
    extern __shared__ float sm[];
    float* Qs = sm;                       // [64][64]
    float* Ks = Qs + 64 * 64;             // [64][65] padded
    float* Vs = Ks + 64 * 65;             // [64][65] padded
    float* Ps = Vs + 64 * 65;             // [64][65] padded
    float* sh_m     = Ps + 64 * 65;
    float* sh_l     = sh_m + 64;
    float* sh_scale = sh_l + 64;

    const int t  = threadIdx.x;
    const int tx = t & 15, ty = t >> 4;
    const int q0 = blockIdx.x * 64;
    const int h  = blockIdx.y;
    const int b  = blockIdx.z;

    const size_t base = (size_t)(b * NH + h) * S_LEN * HD;
    const float* Qp = g_Q + base;
    const float* Kp = g_K + base;
    const float* Vp = g_V + base;

#pragma unroll
    for (int i = 0; i < 16; i++) {
        int idx = t + i * 256;
        int r = idx >> 6, c = idx & 63;
        Qs[r * 64 + c] = Qp[(size_t)(q0 + r) * HD + c];
    }
    if (t < 64) { sh_m[t] = -1e30f; sh_l[t] = 0.f; }

    float acc[4][4] = {};
    __syncthreads();

    for (int j0 = 0; j0 <= q0; j0 += 64) {
#pragma unroll
        for (int i = 0; i < 16; i++) {
            int idx = t + i * 256;
            int r = idx >> 6, c = idx & 63;
            Ks[r * 65 + c] = Kp[(size_t)(j0 + r) * HD + c];
            Vs[r * 65 + c] = Vp[(size_t)(j0 + r) * HD + c];
        }
        __syncthreads();

        // S = Q * K^T  (Q pre-scaled)
        float sv[4][4] = {};
#pragma unroll
        for (int k = 0; k < 64; k++) {
            float a[4], bv[4];
#pragma unroll
            for (int i = 0; i < 4; i++) a[i] = Qs[(ty * 4 + i) * 64 + k];
#pragma unroll
            for (int j = 0; j < 4; j++) bv[j] = Ks[(tx * 4 + j) * 65 + k];
#pragma unroll
            for (int i = 0; i < 4; i++)
#pragma unroll
                for (int j = 0; j < 4; j++)
                    sv[i][j] += a[i] * bv[j];
        }

        const bool diag = (j0 == q0);   // only diagonal tile needs masking
#pragma unroll
        for (int i = 0; i < 4; i++) {
#pragma unroll
            for (int j = 0; j < 4; j++) {
                int r = ty * 4 + i, c = tx * 4 + j;
                float v = sv[i][j];
                if (diag && (c > r)) v = -1e30f;   // kj = j0+c, qi = q0+r, j0==q0
                Ps[r * 65 + c] = v;
            }
        }
        __syncthreads();

        // per-row online softmax (64 rows, threads 0..63)
        if (t < 64) {
            float* row = Ps + t * 65;
            float mo = sh_m[t];
            float mx = mo;
#pragma unroll
            for (int c = 0; c < 64; c++) mx = fmaxf(mx, row[c]);
            float sc  = __expf(mo - mx);
            float sum = 0.f;
#pragma unroll
            for (int c = 0; c < 64; c++) {
                float p = __expf(row[c] - mx);
                row[c] = p;
                sum += p;
            }
            sh_m[t] = mx;
            sh_l[t] = sh_l[t] * sc + sum;
            sh_scale[t] = sc;
        }
        __syncthreads();

        // O = O*scale + P @ V
        float scr[4];
#pragma unroll
        for (int i = 0; i < 4; i++) scr[i] = sh_scale[ty * 4 + i];
#pragma unroll
        for (int i = 0; i < 4; i++)
#pragma unroll
            for (int j = 0; j < 4; j++)
                acc[i][j] *= scr[i];

#pragma unroll
        for (int k = 0; k < 64; k++) {
            float p[4], v[4];
#pragma unroll
            for (int i = 0; i < 4; i++) p[i] = Ps[(ty * 4 + i) * 65 + k];
#pragma unroll
            for (int j = 0; j < 4; j++) v[j] = Vs[k * 65 + tx * 4 + j];
#pragma unroll
            for (int i = 0; i < 4; i++)
#pragma unroll
                for (int j = 0; j < 4; j++)
                    acc[i][j] += p[i] * v[j];
        }
        __syncthreads();
    }

    float linv[4];
#pragma unroll
    for (int i = 0; i < 4; i++) linv[i] = 1.0f / sh_l[ty * 4 + i];
#pragma unroll
    for (int i = 0; i < 4; i++) {
        int r = q0 + ty * 4 + i;
#pragma unroll
        for (int j = 0; j < 4; j++) {
            int d = tx * 4 + j;
            g_Att[((size_t)(b * S_LEN) + r) * E_DIM + h * HD + d] = acc[i][j] * linv[i];
        }
    }
}

// ---------------------------------------------------------------------------
// Kernel 3: output projection.  out[N,768] = Att @ W_out + b_out
// ---------------------------------------------------------------------------
__global__ __launch_bounds__(256) void out_gemm(
    const float* __restrict__ w, const float* __restrict__ bias,
    float* __restrict__ out)
{
    __shared__ float As[64][17];
    __shared__ float Bs[16][64];

    const int t  = threadIdx.x;
    const int tx = t & 15, ty = t >> 4;
    const int row0 = blockIdx.y * 64;
    const int col0 = blockIdx.x * 64;

    float acc[4][4] = {};

    for (int kk = 0; kk < E_DIM; kk += 16) {
#pragma unroll
        for (int i = 0; i < 4; i++) {
            int idx = t + i * 256;
            int r = idx >> 4, c = idx & 15;
            As[r][c] = g_Att[(size_t)(row0 + r) * E_DIM + kk + c];
        }
#pragma unroll
        for (int i = 0; i < 4; i++) {
            int idx = t + i * 256;
            int r = idx >> 6, c = idx & 63;
            Bs[r][c] = w[(size_t)(kk + r) * E_DIM + col0 + c];
        }
        __syncthreads();
#pragma unroll
        for (int k = 0; k < 16; k++) {
            float a[4], bv[4];
#pragma unroll
            for (int i = 0; i < 4; i++) a[i] = As[ty * 4 + i][k];
#pragma unroll
            for (int j = 0; j < 4; j++) bv[j] = Bs[k][tx * 4 + j];
#pragma unroll
            for (int i = 0; i < 4; i++)
#pragma unroll
                for (int j = 0; j < 4; j++)
                    acc[i][j] += a[i] * bv[j];
        }
        __syncthreads();
    }

#pragma unroll
    for (int i = 0; i < 4; i++) {
        int m = row0 + ty * 4 + i;
#pragma unroll
        for (int j = 0; j < 4; j++) {
            int c = col0 + tx * 4 + j;
            out[(size_t)m * E_DIM + c] = acc[i][j] + bias[c];
        }
    }
}

// ---------------------------------------------------------------------------
extern "C" void kernel_launch(void* const* d_in, const int* in_sizes, int n_in,
                              void* d_out, int out_size)
{
    const float* x     = (const float*)d_in[0];
    const float* w_qkv = (const float*)d_in[1];
    const float* b_qkv = (const float*)d_in[2];
    const float* w_out = (const float*)d_in[3];
    const float* b_out = (const float*)d_in[4];
    float* out = (float*)d_out;

    // attention dynamic smem: Qs 64*64 + 3*(64*65) + 3*64 floats
    const int attn_smem = (64 * 64 + 3 * 64 * 65 + 3 * 64) * (int)sizeof(float);
    cudaFuncSetAttribute(attn_kernel,
                         cudaFuncAttributeMaxDynamicSharedMemorySize, attn_smem);

    dim3 g1(QKV_N / 64, NTOK / 64);   // (36, 128)
    qkv_gemm<<<g1, 256>>>(x, w_qkv, b_qkv);

    dim3 g2(S_LEN / 64, NH, BATCH);   // (64, 12, 2)
    attn_kernel<<<g2, 256, attn_smem>>>();

    dim3 g3(E_DIM / 64, NTOK / 64);   // (12, 128)
    out_gemm<<<g3, 256>>>(w_out, b_out, out);
}

// round 2
// speedup vs baseline: 3.2417x; 3.2417x over previous
#include <cuda_runtime.h>

#define S_LEN  4096
#define BATCH  2
#define NH     12
#define HD     64
#define E_DIM  768
#define QKV_N  2304
#define NTOK   (BATCH * S_LEN)

// Scratch (allocation-free rule: __device__ globals)
__device__ float g_Q[(size_t)BATCH * NH * S_LEN * HD];   // pre-scaled by 0.125
__device__ float g_K[(size_t)BATCH * NH * S_LEN * HD];
__device__ float g_V[(size_t)BATCH * NH * S_LEN * HD];
__device__ float g_Att[(size_t)NTOK * E_DIM];            // attended, [B*S, E]

// ---------------------------------------------------------------------------
// tf32 helpers
// ---------------------------------------------------------------------------
__device__ __forceinline__ unsigned f2tf32(float f) {
    unsigned u;
    asm("cvt.rna.tf32.f32 %0, %1;" : "=r"(u) : "f"(f));
    return u;
}

__device__ __forceinline__ void mma_tf32(float c[4],
    unsigned a0, unsigned a1, unsigned a2, unsigned a3,
    unsigned b0, unsigned b1)
{
    asm volatile(
        "mma.sync.aligned.m16n8k8.row.col.f32.tf32.tf32.f32 "
        "{%0,%1,%2,%3}, {%4,%5,%6,%7}, {%8,%9}, {%0,%1,%2,%3};\n"
        : "+f"(c[0]), "+f"(c[1]), "+f"(c[2]), "+f"(c[3])
        : "r"(a0), "r"(a1), "r"(a2), "r"(a3), "r"(b0), "r"(b1));
}

// ---------------------------------------------------------------------------
// Kernel 1: QKV projection. C[8192, 2304] = X @ W + b, scattered to Q/K/V.
// 128x128 tile, BK=16, 8 warps, warp tile 64x32 (mf=4, nf=4). tf32 MMA.
// ---------------------------------------------------------------------------
__global__ __launch_bounds__(256) void qkv_gemm(
    const float* __restrict__ x, const float* __restrict__ w,
    const float* __restrict__ bias)
{
    __shared__ unsigned As[128][20];    // stride 20: conflict-free frag reads
    __shared__ unsigned Bs[16][136];    // stride 136: conflict-free frag reads

    const int t    = threadIdx.x;
    const int lane = t & 31, warp = t >> 5;
    const int gid  = lane >> 2, tig = lane & 3;
    const int wm   = warp >> 2, wn = warp & 3;        // 2 x 4 warp grid
    const int row0 = blockIdx.y * 128;
    const int col0 = blockIdx.x * 128;

    float acc[4][4][4] = {};

    for (int kk = 0; kk < E_DIM; kk += 16) {
#pragma unroll
        for (int i = 0; i < 2; i++) {                 // A tile 128x16
            int idx = t + i * 256;
            int r = idx >> 2, c4 = (idx & 3) * 4;
            float4 v = *(const float4*)&x[(size_t)(row0 + r) * E_DIM + kk + c4];
            uint4 u = make_uint4(f2tf32(v.x), f2tf32(v.y), f2tf32(v.z), f2tf32(v.w));
            *(uint4*)&As[r][c4] = u;
        }
#pragma unroll
        for (int i = 0; i < 2; i++) {                 // B tile 16x128
            int idx = t + i * 256;
            int r = idx >> 5, c4 = (idx & 31) * 4;
            float4 v = *(const float4*)&w[(size_t)(kk + r) * QKV_N + col0 + c4];
            uint4 u = make_uint4(f2tf32(v.x), f2tf32(v.y), f2tf32(v.z), f2tf32(v.w));
            *(uint4*)&Bs[r][c4] = u;
        }
        __syncthreads();

#pragma unroll
        for (int kf = 0; kf < 2; kf++) {
            unsigned a[4][4], b[4][2];
#pragma unroll
            for (int mf = 0; mf < 4; mf++) {
                int m = wm * 64 + mf * 16 + gid;
                a[mf][0] = As[m][kf * 8 + tig];
                a[mf][1] = As[m + 8][kf * 8 + tig];
                a[mf][2] = As[m][kf * 8 + tig + 4];
                a[mf][3] = As[m + 8][kf * 8 + tig + 4];
            }
#pragma unroll
            for (int nf = 0; nf < 4; nf++) {
                int n = wn * 32 + nf * 8 + gid;
                b[nf][0] = Bs[kf * 8 + tig][n];
                b[nf][1] = Bs[kf * 8 + tig + 4][n];
            }
#pragma unroll
            for (int mf = 0; mf < 4; mf++)
#pragma unroll
                for (int nf = 0; nf < 4; nf++)
                    mma_tf32(acc[mf][nf], a[mf][0], a[mf][1], a[mf][2], a[mf][3],
                             b[nf][0], b[nf][1]);
        }
        __syncthreads();
    }

    // Epilogue: bias + scatter. col0 is a multiple of 128, part boundary at 768.
    const int part = col0 / E_DIM;
    float* dst = (part == 0) ? g_Q : (part == 1 ? g_K : g_V);
    const float qs = (part == 0) ? 0.125f : 1.0f;

#pragma unroll
    for (int nf = 0; nf < 4; nf++) {
        int cg = col0 + wn * 32 + nf * 8 + 2 * tig;   // global col (even)
        float b0v = bias[cg], b1v = bias[cg + 1];
        int c = cg % E_DIM;
        int h = c >> 6, d = c & 63;
#pragma unroll
        for (int mf = 0; mf < 4; mf++) {
#pragma unroll
            for (int rr = 0; rr < 2; rr++) {
                int m = row0 + wm * 64 + mf * 16 + gid + rr * 8;
                int bb = m >> 12, s = m & 4095;
                size_t o = ((size_t)(bb * NH + h) * S_LEN + s) * HD + d;
                float2 vv;
                vv.x = (acc[mf][nf][rr * 2]     + b0v) * qs;
                vv.y = (acc[mf][nf][rr * 2 + 1] + b1v) * qs;
                *(float2*)&dst[o] = vv;
            }
        }
    }
}

// ---------------------------------------------------------------------------
// Kernel 2: causal flash attention, tf32 MMA + fp32 softmax.
// grid = (S/128, H, B), 256 threads = 8 warps, each warp owns 16 query rows.
// ---------------------------------------------------------------------------
#define AST 68   // Ps / Q-stage stride (conflict-free)
#define KST 68   // Ks stride
#define VST 72   // Vs stride

__global__ __launch_bounds__(256) void attn_kernel()
{
    extern __shared__ unsigned sm[];
    unsigned* Ks = sm;                    // [64][KST]
    unsigned* Vs = Ks + 64 * KST;         // [64][VST]
    unsigned* Ps = Vs + 64 * VST;         // [128][AST] (also Q staging)

    const int t    = threadIdx.x;
    const int lane = t & 31, warp = t >> 5;
    const int gid  = lane >> 2, tig = lane & 3;
    const int q0   = blockIdx.x * 128;
    const int h    = blockIdx.y;
    const int b    = blockIdx.z;

    const size_t base = (size_t)(b * NH + h) * S_LEN * HD;
    const float* Qp = g_Q + base;
    const float* Kp = g_K + base;
    const float* Vp = g_V + base;

    // ---- stage Q (128x64) into Ps, then load register A-fragments ----
#pragma unroll
    for (int i = 0; i < 8; i++) {
        int idx = t + i * 256;
        int r = idx >> 4, c4 = (idx & 15) * 4;
        float4 v = *(const float4*)&Qp[(size_t)(q0 + r) * HD + c4];
        uint4 u = make_uint4(f2tf32(v.x), f2tf32(v.y), f2tf32(v.z), f2tf32(v.w));
        *(uint4*)&Ps[r * AST + c4] = u;
    }
    __syncthreads();

    const int mrow = warp * 16 + gid;
    unsigned qa[8][4];
#pragma unroll
    for (int kf = 0; kf < 8; kf++) {
        qa[kf][0] = Ps[mrow * AST + kf * 8 + tig];
        qa[kf][1] = Ps[(mrow + 8) * AST + kf * 8 + tig];
        qa[kf][2] = Ps[mrow * AST + kf * 8 + tig + 4];
        qa[kf][3] = Ps[(mrow + 8) * AST + kf * 8 + tig + 4];
    }
    // After this point Ps rows are warp-private (each warp reads/writes only
    // rows [warp*16, warp*16+16)).

    float ml0 = -1e30f, ml1 = -1e30f, l0 = 0.f, l1 = 0.f;
    float o[8][4] = {};

    const int row0g = q0 + warp * 16 + gid;   // global q row of c0/c1
    const int row1g = row0g + 8;              // global q row of c2/c3
    const int wrmin = q0 + warp * 16;
    const int wrmax = wrmin + 15;

    for (int j0 = 0; j0 <= q0 + 64; j0 += 64) {
        __syncthreads();                       // prior iter done with Ks/Vs
#pragma unroll
        for (int i = 0; i < 4; i++) {          // stage K,V (64x64 each)
            int idx = t + i * 256;
            int r = idx >> 4, c4 = (idx & 15) * 4;
            float4 kv = *(const float4*)&Kp[(size_t)(j0 + r) * HD + c4];
            float4 vv = *(const float4*)&Vp[(size_t)(j0 + r) * HD + c4];
            *(uint4*)&Ks[r * KST + c4] =
                make_uint4(f2tf32(kv.x), f2tf32(kv.y), f2tf32(kv.z), f2tf32(kv.w));
            *(uint4*)&Vs[r * VST + c4] =
                make_uint4(f2tf32(vv.x), f2tf32(vv.y), f2tf32(vv.z), f2tf32(vv.w));
        }
        __syncthreads();

        if (j0 <= wrmax) {                     // warp has unmasked work
            // ---- S = Q K^T ----
            float s[8][4] = {};
#pragma unroll
            for (int kf = 0; kf < 8; kf++) {
#pragma unroll
                for (int nf = 0; nf < 8; nf++) {
                    unsigned b0 = Ks[(nf * 8 + gid) * KST + kf * 8 + tig];
                    unsigned b1 = Ks[(nf * 8 + gid) * KST + kf * 8 + tig + 4];
                    mma_tf32(s[nf], qa[kf][0], qa[kf][1], qa[kf][2], qa[kf][3], b0, b1);
                }
            }

            // ---- causal mask (only needed near the diagonal) ----
            if (j0 + 63 > wrmin) {
#pragma unroll
                for (int nf = 0; nf < 8; nf++) {
                    int c = j0 + nf * 8 + 2 * tig;
                    if (c     > row0g) s[nf][0] = -1e30f;
                    if (c + 1 > row0g) s[nf][1] = -1e30f;
                    if (c     > row1g) s[nf][2] = -1e30f;
                    if (c + 1 > row1g) s[nf][3] = -1e30f;
                }
            }

            // ---- online softmax (rows split across the 4-lane quad) ----
            float mx0 = ml0, mx1 = ml1;
#pragma unroll
            for (int nf = 0; nf < 8; nf++) {
                mx0 = fmaxf(mx0, fmaxf(s[nf][0], s[nf][1]));
                mx1 = fmaxf(mx1, fmaxf(s[nf][2], s[nf][3]));
            }
            mx0 = fmaxf(mx0, __shfl_xor_sync(0xffffffffu, mx0, 1));
            mx0 = fmaxf(mx0, __shfl_xor_sync(0xffffffffu, mx0, 2));
            mx1 = fmaxf(mx1, __shfl_xor_sync(0xffffffffu, mx1, 1));
            mx1 = fmaxf(mx1, __shfl_xor_sync(0xffffffffu, mx1, 2));

            float sc0 = __expf(ml0 - mx0), sc1 = __expf(ml1 - mx1);
            float sum0 = 0.f, sum1 = 0.f;
#pragma unroll
            for (int nf = 0; nf < 8; nf++) {
                s[nf][0] = __expf(s[nf][0] - mx0);
                s[nf][1] = __expf(s[nf][1] - mx0);
                s[nf][2] = __expf(s[nf][2] - mx1);
                s[nf][3] = __expf(s[nf][3] - mx1);
                sum0 += s[nf][0] + s[nf][1];
                sum1 += s[nf][2] + s[nf][3];
            }
            sum0 += __shfl_xor_sync(0xffffffffu, sum0, 1);
            sum0 += __shfl_xor_sync(0xffffffffu, sum0, 2);
            sum1 += __shfl_xor_sync(0xffffffffu, sum1, 1);
            sum1 += __shfl_xor_sync(0xffffffffu, sum1, 2);

            l0 = l0 * sc0 + sum0;  l1 = l1 * sc1 + sum1;
            ml0 = mx0;             ml1 = mx1;

#pragma unroll
            for (int nf = 0; nf < 8; nf++) {
                o[nf][0] *= sc0; o[nf][1] *= sc0;
                o[nf][2] *= sc1; o[nf][3] *= sc1;
            }

            // ---- store P (tf32) to warp-private rows of Ps ----
#pragma unroll
            for (int nf = 0; nf < 8; nf++) {
                int cc = nf * 8 + 2 * tig;
                Ps[mrow * AST + cc]           = f2tf32(s[nf][0]);
                Ps[mrow * AST + cc + 1]       = f2tf32(s[nf][1]);
                Ps[(mrow + 8) * AST + cc]     = f2tf32(s[nf][2]);
                Ps[(mrow + 8) * AST + cc + 1] = f2tf32(s[nf][3]);
            }
            __syncwarp();

            // ---- O += P V ----
#pragma unroll
            for (int kf = 0; kf < 8; kf++) {
                unsigned pa0 = Ps[mrow * AST + kf * 8 + tig];
                unsigned pa1 = Ps[(mrow + 8) * AST + kf * 8 + tig];
                unsigned pa2 = Ps[mrow * AST + kf * 8 + tig + 4];
                unsigned pa3 = Ps[(mrow + 8) * AST + kf * 8 + tig + 4];
#pragma unroll
                for (int nf = 0; nf < 8; nf++) {
                    unsigned vb0 = Vs[(kf * 8 + tig) * VST + nf * 8 + gid];
                    unsigned vb1 = Vs[(kf * 8 + tig + 4) * VST + nf * 8 + gid];
                    mma_tf32(o[nf], pa0, pa1, pa2, pa3, vb0, vb1);
                }
            }
            __syncwarp();
        }
    }

    // ---- normalize + write attended [B*S, E] ----
    const float inv0 = 1.0f / l0, inv1 = 1.0f / l1;
#pragma unroll
    for (int nf = 0; nf < 8; nf++) {
        int col = h * HD + nf * 8 + 2 * tig;
        float2 v0 = make_float2(o[nf][0] * inv0, o[nf][1] * inv0);
        float2 v1 = make_float2(o[nf][2] * inv1, o[nf][3] * inv1);
        *(float2*)&g_Att[(size_t)(b * S_LEN + row0g) * E_DIM + col] = v0;
        *(float2*)&g_Att[(size_t)(b * S_LEN + row1g) * E_DIM + col] = v1;
    }
}

// ---------------------------------------------------------------------------
// Kernel 3: output projection. out[8192,768] = Att @ W_out + b_out. tf32 MMA.
// ---------------------------------------------------------------------------
__global__ __launch_bounds__(256) void out_gemm(
    const float* __restrict__ w, const float* __restrict__ bias,
    float* __restrict__ out)
{
    __shared__ unsigned As[128][20];
    __shared__ unsigned Bs[16][136];

    const int t    = threadIdx.x;
    const int lane = t & 31, warp = t >> 5;
    const int gid  = lane >> 2, tig = lane & 3;
    const int wm   = warp >> 2, wn = warp & 3;
    const int row0 = blockIdx.y * 128;
    const int col0 = blockIdx.x * 128;

    float acc[4][4][4] = {};

    for (int kk = 0; kk < E_DIM; kk += 16) {
#pragma unroll
        for (int i = 0; i < 2; i++) {
            int idx = t + i * 256;
            int r = idx >> 2, c4 = (idx & 3) * 4;
            float4 v = *(const float4*)&g_Att[(size_t)(row0 + r) * E_DIM + kk + c4];
            *(uint4*)&As[r][c4] =
                make_uint4(f2tf32(v.x), f2tf32(v.y), f2tf32(v.z), f2tf32(v.w));
        }
#pragma unroll
        for (int i = 0; i < 2; i++) {
            int idx = t + i * 256;
            int r = idx >> 5, c4 = (idx & 31) * 4;
            float4 v = *(const float4*)&w[(size_t)(kk + r) * E_DIM + col0 + c4];
            *(uint4*)&Bs[r][c4] =
                make_uint4(f2tf32(v.x), f2tf32(v.y), f2tf32(v.z), f2tf32(v.w));
        }
        __syncthreads();

#pragma unroll
        for (int kf = 0; kf < 2; kf++) {
            unsigned a[4][4], b[4][2];
#pragma unroll
            for (int mf = 0; mf < 4; mf++) {
                int m = wm * 64 + mf * 16 + gid;
                a[mf][0] = As[m][kf * 8 + tig];
                a[mf][1] = As[m + 8][kf * 8 + tig];
                a[mf][2] = As[m][kf * 8 + tig + 4];
                a[mf][3] = As[m + 8][kf * 8 + tig + 4];
            }
#pragma unroll
            for (int nf = 0; nf < 4; nf++) {
                int n = wn * 32 + nf * 8 + gid;
                b[nf][0] = Bs[kf * 8 + tig][n];
                b[nf][1] = Bs[kf * 8 + tig + 4][n];
            }
#pragma unroll
            for (int mf = 0; mf < 4; mf++)
#pragma unroll
                for (int nf = 0; nf < 4; nf++)
                    mma_tf32(acc[mf][nf], a[mf][0], a[mf][1], a[mf][2], a[mf][3],
                             b[nf][0], b[nf][1]);
        }
        __syncthreads();
    }

#pragma unroll
    for (int nf = 0; nf < 4; nf++) {
        int c = col0 + wn * 32 + nf * 8 + 2 * tig;
        float b0v = bias[c], b1v = bias[c + 1];
#pragma unroll
        for (int mf = 0; mf < 4; mf++) {
#pragma unroll
            for (int rr = 0; rr < 2; rr++) {
                int m = row0 + wm * 64 + mf * 16 + gid + rr * 8;
                float2 vv;
                vv.x = acc[mf][nf][rr * 2]     + b0v;
                vv.y = acc[mf][nf][rr * 2 + 1] + b1v;
                *(float2*)&out[(size_t)m * E_DIM + c] = vv;
            }
        }
    }
}

// ---------------------------------------------------------------------------
extern "C" void kernel_launch(void* const* d_in, const int* in_sizes, int n_in,
                              void* d_out, int out_size)
{
    const float* x     = (const float*)d_in[0];
    const float* w_qkv = (const float*)d_in[1];
    const float* b_qkv = (const float*)d_in[2];
    const float* w_out = (const float*)d_in[3];
    const float* b_out = (const float*)d_in[4];
    float* out = (float*)d_out;

    const int attn_smem = (64 * KST + 64 * VST + 128 * AST) * (int)sizeof(unsigned);
    cudaFuncSetAttribute(attn_kernel,
                         cudaFuncAttributeMaxDynamicSharedMemorySize, attn_smem);

    dim3 g1(QKV_N / 128, NTOK / 128);     // (18, 64)
    qkv_gemm<<<g1, 256>>>(x, w_qkv, b_qkv);

    dim3 g2(S_LEN / 128, NH, BATCH);      // (32, 12, 2)
    attn_kernel<<<g2, 256, attn_smem>>>();

    dim3 g3(E_DIM / 128, NTOK / 128);     // (6, 64)
    out_gemm<<<g3, 256>>>(w_out, b_out, out);
}

// round 4
// speedup vs baseline: 3.9456x; 1.2172x over previous
#include <cuda_runtime.h>

#define S_LEN  4096
#define BATCH  2
#define NH     12
#define HD     64
#define E_DIM  768
#define QKV_N  2304
#define NTOK   (BATCH * S_LEN)
#define NQB    (S_LEN / 128)          // 32 q-blocks per (b,h)

// Scratch (allocation-free rule: __device__ globals). All tf32-pre-rounded.
__device__ float g_Q[(size_t)BATCH * NH * S_LEN * HD];   // pre-scaled by 0.125
__device__ float g_K[(size_t)BATCH * NH * S_LEN * HD];
__device__ float g_V[(size_t)BATCH * NH * S_LEN * HD];
__device__ float g_Att[(size_t)NTOK * E_DIM];            // attended, rounded
__device__ float g_Xr[(size_t)NTOK * E_DIM];             // rounded x
__device__ float g_Wq[(size_t)E_DIM * QKV_N];            // rounded w_qkv
__device__ float g_Wo[(size_t)E_DIM * E_DIM];            // rounded w_out

// ---------------------------------------------------------------------------
// helpers
// ---------------------------------------------------------------------------
__device__ __forceinline__ unsigned f2tf32(float f) {
    unsigned u;
    asm("cvt.rna.tf32.f32 %0, %1;" : "=r"(u) : "f"(f));
    return u;
}
__device__ __forceinline__ float f2tf32f(float f) {
    return __uint_as_float(f2tf32(f));
}

__device__ __forceinline__ void mma_tf32(float c[4],
    unsigned a0, unsigned a1, unsigned a2, unsigned a3,
    unsigned b0, unsigned b1)
{
    asm volatile(
        "mma.sync.aligned.m16n8k8.row.col.f32.tf32.tf32.f32 "
        "{%0,%1,%2,%3}, {%4,%5,%6,%7}, {%8,%9}, {%0,%1,%2,%3};\n"
        : "+f"(c[0]), "+f"(c[1]), "+f"(c[2]), "+f"(c[3])
        : "r"(a0), "r"(a1), "r"(a2), "r"(a3), "r"(b0), "r"(b1));
}

__device__ __forceinline__ void cp16(void* s, const void* g) {
    unsigned sa = (unsigned)__cvta_generic_to_shared(s);
    asm volatile("cp.async.cg.shared.global [%0], [%1], 16;\n" :: "r"(sa), "l"(g));
}
#define CP_COMMIT() asm volatile("cp.async.commit_group;\n")
#define CP_WAIT(N)  asm volatile("cp.async.wait_group %0;\n" :: "n"(N))

// ---------------------------------------------------------------------------
// Kernel 0: pre-round inputs to tf32 (enables raw cp.async staging everywhere)
// ---------------------------------------------------------------------------
__global__ void prepass(const float* __restrict__ x,
                        const float* __restrict__ wq,
                        const float* __restrict__ wo)
{
    const int stride = gridDim.x * blockDim.x;
    const int tid = blockIdx.x * blockDim.x + threadIdx.x;
    const int nx = NTOK * E_DIM / 4, nq = E_DIM * QKV_N / 4, no = E_DIM * E_DIM / 4;
    for (int i = tid; i < nx; i += stride) {
        float4 v = ((const float4*)x)[i];
        ((float4*)g_Xr)[i] = make_float4(f2tf32f(v.x), f2tf32f(v.y), f2tf32f(v.z), f2tf32f(v.w));
    }
    for (int i = tid; i < nq; i += stride) {
        float4 v = ((const float4*)wq)[i];
        ((float4*)g_Wq)[i] = make_float4(f2tf32f(v.x), f2tf32f(v.y), f2tf32f(v.z), f2tf32f(v.w));
    }
    for (int i = tid; i < no; i += stride) {
        float4 v = ((const float4*)wo)[i];
        ((float4*)g_Wo)[i] = make_float4(f2tf32f(v.x), f2tf32f(v.y), f2tf32f(v.z), f2tf32f(v.w));
    }
}

// ---------------------------------------------------------------------------
// Kernel 1: QKV projection. C[8192,2304] = Xr @ Wq + b, scatter to Q/K/V.
// 128x128 tile, BK=16, double-buffered cp.async, tf32 MMA.
// ---------------------------------------------------------------------------
__global__ __launch_bounds__(256) void qkv_gemm(const float* __restrict__ bias)
{
    __shared__ unsigned As[2][128][20];
    __shared__ unsigned Bs[2][16][136];

    const int t    = threadIdx.x;
    const int lane = t & 31, warp = t >> 5;
    const int gid  = lane >> 2, tig = lane & 3;
    const int wm   = warp >> 2, wn = warp & 3;
    const int row0 = blockIdx.y * 128;
    const int col0 = blockIdx.x * 128;

    float acc[4][4][4] = {};

    auto stage = [&](int buf, int kk) {
#pragma unroll
        for (int i = 0; i < 2; i++) {
            int c = t + i * 256;
            int rr = c >> 2, c4 = (c & 3) * 4;
            cp16(&As[buf][rr][c4], &g_Xr[(size_t)(row0 + rr) * E_DIM + kk + c4]);
        }
#pragma unroll
        for (int i = 0; i < 2; i++) {
            int c = t + i * 256;
            int rr = c >> 5, c4 = (c & 31) * 4;
            cp16(&Bs[buf][rr][c4], &g_Wq[(size_t)(kk + rr) * QKV_N + col0 + c4]);
        }
        CP_COMMIT();
    };

    stage(0, 0);
    const int NT = E_DIM / 16;
    for (int it = 0; it < NT; it++) {
        if (it + 1 < NT) { stage((it + 1) & 1, (it + 1) * 16); CP_WAIT(1); }
        else             { CP_WAIT(0); }
        __syncthreads();
        const int buf = it & 1;
#pragma unroll
        for (int kf = 0; kf < 2; kf++) {
            unsigned a[4][4], b[4][2];
#pragma unroll
            for (int mf = 0; mf < 4; mf++) {
                int m = wm * 64 + mf * 16 + gid;
                a[mf][0] = As[buf][m][kf * 8 + tig];
                a[mf][1] = As[buf][m + 8][kf * 8 + tig];
                a[mf][2] = As[buf][m][kf * 8 + tig + 4];
                a[mf][3] = As[buf][m + 8][kf * 8 + tig + 4];
            }
#pragma unroll
            for (int nf = 0; nf < 4; nf++) {
                int n = wn * 32 + nf * 8 + gid;
                b[nf][0] = Bs[buf][kf * 8 + tig][n];
                b[nf][1] = Bs[buf][kf * 8 + tig + 4][n];
            }
#pragma unroll
            for (int mf = 0; mf < 4; mf++)
#pragma unroll
                for (int nf = 0; nf < 4; nf++)
                    mma_tf32(acc[mf][nf], a[mf][0], a[mf][1], a[mf][2], a[mf][3],
                             b[nf][0], b[nf][1]);
        }
        __syncthreads();
    }

    // Epilogue: bias + tf32 round + scatter to Q/K/V [B,H,S,D]
    const int part = col0 / E_DIM;
    float* dst = (part == 0) ? g_Q : (part == 1 ? g_K : g_V);
    const float qs = (part == 0) ? 0.125f : 1.0f;

#pragma unroll
    for (int nf = 0; nf < 4; nf++) {
        int cg = col0 + wn * 32 + nf * 8 + 2 * tig;
        float b0v = bias[cg], b1v = bias[cg + 1];
        int c = cg % E_DIM;
        int h = c >> 6, d = c & 63;
#pragma unroll
        for (int mf = 0; mf < 4; mf++) {
#pragma unroll
            for (int rr = 0; rr < 2; rr++) {
                int m = row0 + wm * 64 + mf * 16 + gid + rr * 8;
                int bb = m >> 12, s = m & 4095;
                size_t o = ((size_t)(bb * NH + h) * S_LEN + s) * HD + d;
                float2 vv;
                vv.x = f2tf32f((acc[mf][nf][rr * 2]     + b0v) * qs);
                vv.y = f2tf32f((acc[mf][nf][rr * 2 + 1] + b1v) * qs);
                *(float2*)&dst[o] = vv;
            }
        }
    }
}

// ---------------------------------------------------------------------------
// Kernel 2: causal flash attention, tf32 MMA + fp32 softmax.
// 1-D grid of 768, sizes globally DESCENDING for load balance.
// 256 threads = 8 warps, each warp owns 16 query rows. cp.async K/V staging.
// ---------------------------------------------------------------------------
#define AST 68
#define KST 68
#define VST 72

__global__ __launch_bounds__(256) void attn_kernel()
{
    extern __shared__ unsigned sm[];
    unsigned* Ks = sm;                    // [64][KST]
    unsigned* Vs = Ks + 64 * KST;         // [64][VST]
    unsigned* Ps = Vs + 64 * VST;         // [128][AST] (also Q staging)

    const int t    = threadIdx.x;
    const int lane = t & 31, warp = t >> 5;
    const int gid  = lane >> 2, tig = lane & 3;

    // descending-size schedule: biggest q-blocks first
    const int r  = blockIdx.x;
    const int qb = (NQB - 1) - r / (NH * BATCH);
    const int hb = r % (NH * BATCH);
    const int h  = hb % NH;
    const int b  = hb / NH;
    const int q0 = qb * 128;

    const size_t base = (size_t)(b * NH + h) * S_LEN * HD;
    const float* Qp = g_Q + base;
    const float* Kp = g_K + base;
    const float* Vp = g_V + base;

    // ---- stage Q (128x64, pre-rounded) via cp.async into Ps ----
#pragma unroll
    for (int i = 0; i < 8; i++) {
        int c = t + i * 256;
        int row = c >> 4, c4 = (c & 15) * 4;
        cp16(&Ps[row * AST + c4], &Qp[(size_t)(q0 + row) * HD + c4]);
    }
    CP_COMMIT();
    CP_WAIT(0);
    __syncthreads();

    const int mrow = warp * 16 + gid;
    unsigned qa[8][4];
#pragma unroll
    for (int kf = 0; kf < 8; kf++) {
        qa[kf][0] = Ps[mrow * AST + kf * 8 + tig];
        qa[kf][1] = Ps[(mrow + 8) * AST + kf * 8 + tig];
        qa[kf][2] = Ps[mrow * AST + kf * 8 + tig + 4];
        qa[kf][3] = Ps[(mrow + 8) * AST + kf * 8 + tig + 4];
    }

    float ml0 = -1e30f, ml1 = -1e30f, l0 = 0.f, l1 = 0.f;
    float o[8][4] = {};

    const int row0g = q0 + warp * 16 + gid;
    const int row1g = row0g + 8;
    const int wrmin = q0 + warp * 16;
    const int wrmax = wrmin + 15;

    for (int j0 = 0; j0 <= q0 + 64; j0 += 64) {
        __syncthreads();                       // prev iter done with Ks/Vs
        // issue K then V as separate cp.async groups
#pragma unroll
        for (int i = 0; i < 4; i++) {
            int c = t + i * 256;
            int row = c >> 4, c4 = (c & 15) * 4;
            cp16(&Ks[row * KST + c4], &Kp[(size_t)(j0 + row) * HD + c4]);
        }
        CP_COMMIT();
#pragma unroll
        for (int i = 0; i < 4; i++) {
            int c = t + i * 256;
            int row = c >> 4, c4 = (c & 15) * 4;
            cp16(&Vs[row * VST + c4], &Vp[(size_t)(j0 + row) * HD + c4]);
        }
        CP_COMMIT();

        CP_WAIT(1);                            // K ready (V may be in flight)
        __syncthreads();

        const bool work = (j0 <= wrmax);
        if (work) {
            // ---- S = Q K^T ----
            float s[8][4] = {};
#pragma unroll
            for (int kf = 0; kf < 8; kf++) {
#pragma unroll
                for (int nf = 0; nf < 8; nf++) {
                    unsigned b0 = Ks[(nf * 8 + gid) * KST + kf * 8 + tig];
                    unsigned b1 = Ks[(nf * 8 + gid) * KST + kf * 8 + tig + 4];
                    mma_tf32(s[nf], qa[kf][0], qa[kf][1], qa[kf][2], qa[kf][3], b0, b1);
                }
            }

            // ---- causal mask (only near the diagonal) ----
            if (j0 + 63 > wrmin) {
#pragma unroll
                for (int nf = 0; nf < 8; nf++) {
                    int c = j0 + nf * 8 + 2 * tig;
                    if (c     > row0g) s[nf][0] = -1e30f;
                    if (c + 1 > row0g) s[nf][1] = -1e30f;
                    if (c     > row1g) s[nf][2] = -1e30f;
                    if (c + 1 > row1g) s[nf][3] = -1e30f;
                }
            }

            // ---- online softmax ----
            float mx0 = ml0, mx1 = ml1;
#pragma unroll
            for (int nf = 0; nf < 8; nf++) {
                mx0 = fmaxf(mx0, fmaxf(s[nf][0], s[nf][1]));
                mx1 = fmaxf(mx1, fmaxf(s[nf][2], s[nf][3]));
            }
            mx0 = fmaxf(mx0, __shfl_xor_sync(0xffffffffu, mx0, 1));
            mx0 = fmaxf(mx0, __shfl_xor_sync(0xffffffffu, mx0, 2));
            mx1 = fmaxf(mx1, __shfl_xor_sync(0xffffffffu, mx1, 1));
            mx1 = fmaxf(mx1, __shfl_xor_sync(0xffffffffu, mx1, 2));

            float sc0 = __expf(ml0 - mx0), sc1 = __expf(ml1 - mx1);
            float sum0 = 0.f, sum1 = 0.f;
#pragma unroll
            for (int nf = 0; nf < 8; nf++) {
                s[nf][0] = __expf(s[nf][0] - mx0);
                s[nf][1] = __expf(s[nf][1] - mx0);
                s[nf][2] = __expf(s[nf][2] - mx1);
                s[nf][3] = __expf(s[nf][3] - mx1);
                sum0 += s[nf][0] + s[nf][1];
                sum1 += s[nf][2] + s[nf][3];
            }
            sum0 += __shfl_xor_sync(0xffffffffu, sum0, 1);
            sum0 += __shfl_xor_sync(0xffffffffu, sum0, 2);
            sum1 += __shfl_xor_sync(0xffffffffu, sum1, 1);
            sum1 += __shfl_xor_sync(0xffffffffu, sum1, 2);

            l0 = l0 * sc0 + sum0;  l1 = l1 * sc1 + sum1;
            ml0 = mx0;             ml1 = mx1;

#pragma unroll
            for (int nf = 0; nf < 8; nf++) {
                o[nf][0] *= sc0; o[nf][1] *= sc0;
                o[nf][2] *= sc1; o[nf][3] *= sc1;
            }

            // ---- store P (tf32) to warp-private rows of Ps ----
#pragma unroll
            for (int nf = 0; nf < 8; nf++) {
                int cc = nf * 8 + 2 * tig;
                Ps[mrow * AST + cc]           = f2tf32(s[nf][0]);
                Ps[mrow * AST + cc + 1]       = f2tf32(s[nf][1]);
                Ps[(mrow + 8) * AST + cc]     = f2tf32(s[nf][2]);
                Ps[(mrow + 8) * AST + cc + 1] = f2tf32(s[nf][3]);
            }
            __syncwarp();
        }

        CP_WAIT(0);                            // V ready
        __syncthreads();

        if (work) {
            // ---- O += P V ----
#pragma unroll
            for (int kf = 0; kf < 8; kf++) {
                unsigned pa0 = Ps[mrow * AST + kf * 8 + tig];
                unsigned pa1 = Ps[(mrow + 8) * AST + kf * 8 + tig];
                unsigned pa2 = Ps[mrow * AST + kf * 8 + tig + 4];
                unsigned pa3 = Ps[(mrow + 8) * AST + kf * 8 + tig + 4];
#pragma unroll
                for (int nf = 0; nf < 8; nf++) {
                    unsigned vb0 = Vs[(kf * 8 + tig) * VST + nf * 8 + gid];
                    unsigned vb1 = Vs[(kf * 8 + tig + 4) * VST + nf * 8 + gid];
                    mma_tf32(o[nf], pa0, pa1, pa2, pa3, vb0, vb1);
                }
            }
        }
    }

    // ---- normalize + round + write attended [B*S, E] ----
    const float inv0 = 1.0f / l0, inv1 = 1.0f / l1;
#pragma unroll
    for (int nf = 0; nf < 8; nf++) {
        int col = h * HD + nf * 8 + 2 * tig;
        float2 v0 = make_float2(f2tf32f(o[nf][0] * inv0), f2tf32f(o[nf][1] * inv0));
        float2 v1 = make_float2(f2tf32f(o[nf][2] * inv1), f2tf32f(o[nf][3] * inv1));
        *(float2*)&g_Att[(size_t)(b * S_LEN + row0g) * E_DIM + col] = v0;
        *(float2*)&g_Att[(size_t)(b * S_LEN + row1g) * E_DIM + col] = v1;
    }
}

// ---------------------------------------------------------------------------
// Kernel 3: output projection. out[8192,768] = Att @ Wo + b_out. tf32 MMA.
// ---------------------------------------------------------------------------
__global__ __launch_bounds__(256) void out_gemm(
    const float* __restrict__ bias, float* __restrict__ out)
{
    __shared__ unsigned As[2][128][20];
    __shared__ unsigned Bs[2][16][136];

    const int t    = threadIdx.x;
    const int lane = t & 31, warp = t >> 5;
    const int gid  = lane >> 2, tig = lane & 3;
    const int wm   = warp >> 2, wn = warp & 3;
    const int row0 = blockIdx.y * 128;
    const int col0 = blockIdx.x * 128;

    float acc[4][4][4] = {};

    auto stage = [&](int buf, int kk) {
#pragma unroll
        for (int i = 0; i < 2; i++) {
            int c = t + i * 256;
            int rr = c >> 2, c4 = (c & 3) * 4;
            cp16(&As[buf][rr][c4], &g_Att[(size_t)(row0 + rr) * E_DIM + kk + c4]);
        }
#pragma unroll
        for (int i = 0; i < 2; i++) {
            int c = t + i * 256;
            int rr = c >> 5, c4 = (c & 31) * 4;
            cp16(&Bs[buf][rr][c4], &g_Wo[(size_t)(kk + rr) * E_DIM + col0 + c4]);
        }
        CP_COMMIT();
    };

    stage(0, 0);
    const int NT = E_DIM / 16;
    for (int it = 0; it < NT; it++) {
        if (it + 1 < NT) { stage((it + 1) & 1, (it + 1) * 16); CP_WAIT(1); }
        else             { CP_WAIT(0); }
        __syncthreads();
        const int buf = it & 1;
#pragma unroll
        for (int kf = 0; kf < 2; kf++) {
            unsigned a[4][4], b[4][2];
#pragma unroll
            for (int mf = 0; mf < 4; mf++) {
                int m = wm * 64 + mf * 16 + gid;
                a[mf][0] = As[buf][m][kf * 8 + tig];
                a[mf][1] = As[buf][m + 8][kf * 8 + tig];
                a[mf][2] = As[buf][m][kf * 8 + tig + 4];
                a[mf][3] = As[buf][m + 8][kf * 8 + tig + 4];
            }
#pragma unroll
            for (int nf = 0; nf < 4; nf++) {
                int n = wn * 32 + nf * 8 + gid;
                b[nf][0] = Bs[buf][kf * 8 + tig][n];
                b[nf][1] = Bs[buf][kf * 8 + tig + 4][n];
            }
#pragma unroll
            for (int mf = 0; mf < 4; mf++)
#pragma unroll
                for (int nf = 0; nf < 4; nf++)
                    mma_tf32(acc[mf][nf], a[mf][0], a[mf][1], a[mf][2], a[mf][3],
                             b[nf][0], b[nf][1]);
        }
        __syncthreads();
    }

#pragma unroll
    for (int nf = 0; nf < 4; nf++) {
        int c = col0 + wn * 32 + nf * 8 + 2 * tig;
        float b0v = bias[c], b1v = bias[c + 1];
#pragma unroll
        for (int mf = 0; mf < 4; mf++) {
#pragma unroll
            for (int rr = 0; rr < 2; rr++) {
                int m = row0 + wm * 64 + mf * 16 + gid + rr * 8;
                float2 vv;
                vv.x = acc[mf][nf][rr * 2]     + b0v;
                vv.y = acc[mf][nf][rr * 2 + 1] + b1v;
                *(float2*)&out[(size_t)m * E_DIM + c] = vv;
            }
        }
    }
}

// ---------------------------------------------------------------------------
extern "C" void kernel_launch(void* const* d_in, const int* in_sizes, int n_in,
                              void* d_out, int out_size)
{
    const float* x     = (const float*)d_in[0];
    const float* w_qkv = (const float*)d_in[1];
    const float* b_qkv = (const float*)d_in[2];
    const float* w_out = (const float*)d_in[3];
    const float* b_out = (const float*)d_in[4];
    float* out = (float*)d_out;

    const int attn_smem = (64 * KST + 64 * VST + 128 * AST) * (int)sizeof(unsigned);
    cudaFuncSetAttribute(attn_kernel,
                         cudaFuncAttributeMaxDynamicSharedMemorySize, attn_smem);

    prepass<<<1024, 256>>>(x, w_qkv, w_out);

    dim3 g1(QKV_N / 128, NTOK / 128);     // (18, 64)
    qkv_gemm<<<g1, 256>>>(b_qkv);

    attn_kernel<<<NQB * NH * BATCH, 256, attn_smem>>>();   // 768, descending

    dim3 g3(E_DIM / 128, NTOK / 128);     // (6, 64)
    out_gemm<<<g3, 256>>>(b_out, out);
}

// round 5
// speedup vs baseline: 4.6029x; 1.1666x over previous
#include <cuda_runtime.h>

#define S_LEN  4096
#define BATCH  2
#define NH     12
#define HD     64
#define E_DIM  768
#define QKV_N  2304
#define NTOK   (BATCH * S_LEN)
#define NQB    (S_LEN / 128)          // 32 q-blocks per (b,h)

// Scratch (allocation-free rule: __device__ globals). All tf32-pre-rounded.
__device__ float g_Q[(size_t)BATCH * NH * S_LEN * HD];   // pre-scaled by 0.125*log2e
__device__ float g_K[(size_t)BATCH * NH * S_LEN * HD];
__device__ float g_V[(size_t)BATCH * NH * S_LEN * HD];
__device__ float g_Att[(size_t)NTOK * E_DIM];            // attended, rounded
__device__ float g_Xr[(size_t)NTOK * E_DIM];             // rounded x
__device__ float g_Wq[(size_t)E_DIM * QKV_N];            // rounded w_qkv
__device__ float g_Wo[(size_t)E_DIM * E_DIM];            // rounded w_out

// ---------------------------------------------------------------------------
// helpers
// ---------------------------------------------------------------------------
__device__ __forceinline__ unsigned f2tf32(float f) {
    unsigned u;
    asm("cvt.rna.tf32.f32 %0, %1;" : "=r"(u) : "f"(f));
    return u;
}
__device__ __forceinline__ float f2tf32f(float f) {
    return __uint_as_float(f2tf32(f));
}
__device__ __forceinline__ float ex2f(float x) {
    float y;
    asm("ex2.approx.f32 %0, %1;" : "=f"(y) : "f"(x));
    return y;
}

__device__ __forceinline__ void mma_tf32(float c[4],
    unsigned a0, unsigned a1, unsigned a2, unsigned a3,
    unsigned b0, unsigned b1)
{
    asm volatile(
        "mma.sync.aligned.m16n8k8.row.col.f32.tf32.tf32.f32 "
        "{%0,%1,%2,%3}, {%4,%5,%6,%7}, {%8,%9}, {%0,%1,%2,%3};\n"
        : "+f"(c[0]), "+f"(c[1]), "+f"(c[2]), "+f"(c[3])
        : "r"(a0), "r"(a1), "r"(a2), "r"(a3), "r"(b0), "r"(b1));
}

__device__ __forceinline__ void cp16(void* s, const void* g) {
    unsigned sa = (unsigned)__cvta_generic_to_shared(s);
    asm volatile("cp.async.cg.shared.global [%0], [%1], 16;\n" :: "r"(sa), "l"(g));
}
#define CP_COMMIT() asm volatile("cp.async.commit_group;\n")
#define CP_WAIT(N)  asm volatile("cp.async.wait_group %0;\n" :: "n"(N))

// scale folded into Q: 1/sqrt(64) * log2(e)
#define QSCALE 0.1803368801111204f

// ---------------------------------------------------------------------------
// Kernel 0: pre-round inputs to tf32 (enables raw cp.async staging everywhere)
// ---------------------------------------------------------------------------
__global__ void prepass(const float* __restrict__ x,
                        const float* __restrict__ wq,
                        const float* __restrict__ wo)
{
    const int stride = gridDim.x * blockDim.x;
    const int tid = blockIdx.x * blockDim.x + threadIdx.x;
    const int nx = NTOK * E_DIM / 4, nq = E_DIM * QKV_N / 4, no = E_DIM * E_DIM / 4;
    for (int i = tid; i < nx; i += stride) {
        float4 v = ((const float4*)x)[i];
        ((float4*)g_Xr)[i] = make_float4(f2tf32f(v.x), f2tf32f(v.y), f2tf32f(v.z), f2tf32f(v.w));
    }
    for (int i = tid; i < nq; i += stride) {
        float4 v = ((const float4*)wq)[i];
        ((float4*)g_Wq)[i] = make_float4(f2tf32f(v.x), f2tf32f(v.y), f2tf32f(v.z), f2tf32f(v.w));
    }
    for (int i = tid; i < no; i += stride) {
        float4 v = ((const float4*)wo)[i];
        ((float4*)g_Wo)[i] = make_float4(f2tf32f(v.x), f2tf32f(v.y), f2tf32f(v.z), f2tf32f(v.w));
    }
}

// ---------------------------------------------------------------------------
// Kernel 1: QKV projection. C[8192,2304] = Xr @ Wq + b, scatter to Q/K/V.
// 128x128 tile, BK=16, 3-stage cp.async pipeline, tf32 MMA. Dynamic smem.
// ---------------------------------------------------------------------------
#define GA_ST 20
#define GB_ST 136
#define GA_SZ (128 * GA_ST)
#define GB_SZ (16 * GB_ST)
#define GEMM_SMEM (3 * (GA_SZ + GB_SZ) * 4)

__global__ __launch_bounds__(256) void qkv_gemm(const float* __restrict__ bias)
{
    extern __shared__ unsigned smg[];
    unsigned* Asb = smg;                 // [3][128][GA_ST]
    unsigned* Bsb = smg + 3 * GA_SZ;     // [3][16][GB_ST]

    const int t    = threadIdx.x;
    const int lane = t & 31, warp = t >> 5;
    const int gid  = lane >> 2, tig = lane & 3;
    const int wm   = warp >> 2, wn = warp & 3;
    const int row0 = blockIdx.y * 128;
    const int col0 = blockIdx.x * 128;

    float acc[4][4][4] = {};

    auto stage = [&](int buf, int kk) {
        unsigned* A = Asb + buf * GA_SZ;
        unsigned* B = Bsb + buf * GB_SZ;
#pragma unroll
        for (int i = 0; i < 2; i++) {
            int c = t + i * 256;
            int rr = c >> 2, c4 = (c & 3) * 4;
            cp16(&A[rr * GA_ST + c4], &g_Xr[(size_t)(row0 + rr) * E_DIM + kk + c4]);
        }
#pragma unroll
        for (int i = 0; i < 2; i++) {
            int c = t + i * 256;
            int rr = c >> 5, c4 = (c & 31) * 4;
            cp16(&B[rr * GB_ST + c4], &g_Wq[(size_t)(kk + rr) * QKV_N + col0 + c4]);
        }
        CP_COMMIT();
    };

    const int NT = E_DIM / 16;   // 48
    stage(0, 0);
    stage(1, 16);
    int buf = 0;
    for (int it = 0; it < NT; it++) {
        if (it + 2 < NT)      { stage((it + 2) % 3, (it + 2) * 16); CP_WAIT(2); }
        else if (it + 1 < NT) { CP_WAIT(1); }
        else                  { CP_WAIT(0); }
        __syncthreads();
        unsigned* A = Asb + buf * GA_SZ;
        unsigned* B = Bsb + buf * GB_SZ;
#pragma unroll
        for (int kf = 0; kf < 2; kf++) {
            unsigned a[4][4], b[4][2];
#pragma unroll
            for (int mf = 0; mf < 4; mf++) {
                int m = wm * 64 + mf * 16 + gid;
                a[mf][0] = A[m * GA_ST + kf * 8 + tig];
                a[mf][1] = A[(m + 8) * GA_ST + kf * 8 + tig];
                a[mf][2] = A[m * GA_ST + kf * 8 + tig + 4];
                a[mf][3] = A[(m + 8) * GA_ST + kf * 8 + tig + 4];
            }
#pragma unroll
            for (int nf = 0; nf < 4; nf++) {
                int n = wn * 32 + nf * 8 + gid;
                b[nf][0] = B[(kf * 8 + tig) * GB_ST + n];
                b[nf][1] = B[(kf * 8 + tig + 4) * GB_ST + n];
            }
#pragma unroll
            for (int mf = 0; mf < 4; mf++)
#pragma unroll
                for (int nf = 0; nf < 4; nf++)
                    mma_tf32(acc[mf][nf], a[mf][0], a[mf][1], a[mf][2], a[mf][3],
                             b[nf][0], b[nf][1]);
        }
        __syncthreads();
        buf = (buf + 1) % 3;
    }

    // Epilogue: bias + tf32 round + scatter to Q/K/V [B,H,S,D]
    const int part = col0 / E_DIM;
    float* dst = (part == 0) ? g_Q : (part == 1 ? g_K : g_V);
    const float qs = (part == 0) ? QSCALE : 1.0f;

#pragma unroll
    for (int nf = 0; nf < 4; nf++) {
        int cg = col0 + wn * 32 + nf * 8 + 2 * tig;
        float b0v = bias[cg], b1v = bias[cg + 1];
        int c = cg % E_DIM;
        int h = c >> 6, d = c & 63;
#pragma unroll
        for (int mf = 0; mf < 4; mf++) {
#pragma unroll
            for (int rr = 0; rr < 2; rr++) {
                int m = row0 + wm * 64 + mf * 16 + gid + rr * 8;
                int bb = m >> 12, s = m & 4095;
                size_t o = ((size_t)(bb * NH + h) * S_LEN + s) * HD + d;
                float2 vv;
                vv.x = f2tf32f((acc[mf][nf][rr * 2]     + b0v) * qs);
                vv.y = f2tf32f((acc[mf][nf][rr * 2 + 1] + b1v) * qs);
                *(float2*)&dst[o] = vv;
            }
        }
    }
}

// ---------------------------------------------------------------------------
// Kernel 2: causal flash attention, tf32 MMA + log2-domain softmax.
// Double-buffered cp.async K/V (latency fully hidden), descending schedule.
// 256 threads = 8 warps, each warp owns 16 query rows.
// ---------------------------------------------------------------------------
#define AST 68
#define KST 68
#define VST 72
#define KBUF (64 * KST)
#define VBUF (64 * VST)
#define ATTN_SMEM ((2 * KBUF + 2 * VBUF + 128 * AST) * 4)

__global__ __launch_bounds__(256) void attn_kernel()
{
    extern __shared__ unsigned sm[];
    unsigned* Ksb = sm;                       // [2][64][KST]
    unsigned* Vsb = sm + 2 * KBUF;            // [2][64][VST]
    unsigned* Ps  = sm + 2 * KBUF + 2 * VBUF; // [128][AST] (also Q staging)

    const int t    = threadIdx.x;
    const int lane = t & 31, warp = t >> 5;
    const int gid  = lane >> 2, tig = lane & 3;

    // descending-size schedule: biggest q-blocks first
    const int r  = blockIdx.x;
    const int qb = (NQB - 1) - r / (NH * BATCH);
    const int hb = r % (NH * BATCH);
    const int h  = hb % NH;
    const int b  = hb / NH;
    const int q0 = qb * 128;

    const size_t base = (size_t)(b * NH + h) * S_LEN * HD;
    const float* Qp = g_Q + base;
    const float* Kp = g_K + base;
    const float* Vp = g_V + base;

    auto stage_kv = [&](int buf, int j0) {
        unsigned* K = Ksb + buf * KBUF;
        unsigned* V = Vsb + buf * VBUF;
#pragma unroll
        for (int i = 0; i < 4; i++) {
            int c = t + i * 256;
            int row = c >> 4, c4 = (c & 15) * 4;
            cp16(&K[row * KST + c4], &Kp[(size_t)(j0 + row) * HD + c4]);
            cp16(&V[row * VST + c4], &Vp[(size_t)(j0 + row) * HD + c4]);
        }
        CP_COMMIT();
    };

    // ---- stage Q (128x64, pre-rounded) via cp.async into Ps ----
#pragma unroll
    for (int i = 0; i < 8; i++) {
        int c = t + i * 256;
        int row = c >> 4, c4 = (c & 15) * 4;
        cp16(&Ps[row * AST + c4], &Qp[(size_t)(q0 + row) * HD + c4]);
    }
    CP_COMMIT();
    stage_kv(0, 0);                       // prefetch KV tile 0 behind Q
    CP_WAIT(1);                           // Q ready; KV0 may be in flight
    __syncthreads();

    const int mrow = warp * 16 + gid;
    unsigned qa[8][4];
#pragma unroll
    for (int kf = 0; kf < 8; kf++) {
        qa[kf][0] = Ps[mrow * AST + kf * 8 + tig];
        qa[kf][1] = Ps[(mrow + 8) * AST + kf * 8 + tig];
        qa[kf][2] = Ps[mrow * AST + kf * 8 + tig + 4];
        qa[kf][3] = Ps[(mrow + 8) * AST + kf * 8 + tig + 4];
    }

    float ml0 = -1e30f, ml1 = -1e30f, l0 = 0.f, l1 = 0.f;
    float o[8][4] = {};

    const int row0g = q0 + warp * 16 + gid;
    const int row1g = row0g + 8;
    const int wrmin = q0 + warp * 16;
    const int wrmax = wrmin + 15;
    const int jmax  = q0 + 64;

    for (int j0 = 0; j0 <= jmax; j0 += 64) {
        const int buf = (j0 >> 6) & 1;
        if (j0 + 64 <= jmax) { stage_kv(buf ^ 1, j0 + 64); CP_WAIT(1); }
        else                 { CP_WAIT(0); }
        __syncthreads();

        if (j0 <= wrmax) {
            const unsigned* Ks = Ksb + buf * KBUF;
            const unsigned* Vs = Vsb + buf * VBUF;

            // ---- S = Q K^T (log2-scaled: Q pre-scaled by 0.125*log2e) ----
            float s[8][4] = {};
#pragma unroll
            for (int kf = 0; kf < 8; kf++) {
#pragma unroll
                for (int nf = 0; nf < 8; nf++) {
                    unsigned b0 = Ks[(nf * 8 + gid) * KST + kf * 8 + tig];
                    unsigned b1 = Ks[(nf * 8 + gid) * KST + kf * 8 + tig + 4];
                    mma_tf32(s[nf], qa[kf][0], qa[kf][1], qa[kf][2], qa[kf][3], b0, b1);
                }
            }

            // ---- causal mask (only near the diagonal) ----
            if (j0 + 63 > wrmin) {
#pragma unroll
                for (int nf = 0; nf < 8; nf++) {
                    int c = j0 + nf * 8 + 2 * tig;
                    if (c     > row0g) s[nf][0] = -1e30f;
                    if (c + 1 > row0g) s[nf][1] = -1e30f;
                    if (c     > row1g) s[nf][2] = -1e30f;
                    if (c + 1 > row1g) s[nf][3] = -1e30f;
                }
            }

            // ---- online softmax, base-2 ----
            float mx0 = ml0, mx1 = ml1;
#pragma unroll
            for (int nf = 0; nf < 8; nf++) {
                mx0 = fmaxf(mx0, fmaxf(s[nf][0], s[nf][1]));
                mx1 = fmaxf(mx1, fmaxf(s[nf][2], s[nf][3]));
            }
            mx0 = fmaxf(mx0, __shfl_xor_sync(0xffffffffu, mx0, 1));
            mx0 = fmaxf(mx0, __shfl_xor_sync(0xffffffffu, mx0, 2));
            mx1 = fmaxf(mx1, __shfl_xor_sync(0xffffffffu, mx1, 1));
            mx1 = fmaxf(mx1, __shfl_xor_sync(0xffffffffu, mx1, 2));

            float sc0 = ex2f(ml0 - mx0), sc1 = ex2f(ml1 - mx1);
            float sum0 = 0.f, sum1 = 0.f;
#pragma unroll
            for (int nf = 0; nf < 8; nf++) {
                s[nf][0] = ex2f(s[nf][0] - mx0);
                s[nf][1] = ex2f(s[nf][1] - mx0);
                s[nf][2] = ex2f(s[nf][2] - mx1);
                s[nf][3] = ex2f(s[nf][3] - mx1);
                sum0 += s[nf][0] + s[nf][1];
                sum1 += s[nf][2] + s[nf][3];
            }
            sum0 += __shfl_xor_sync(0xffffffffu, sum0, 1);
            sum0 += __shfl_xor_sync(0xffffffffu, sum0, 2);
            sum1 += __shfl_xor_sync(0xffffffffu, sum1, 1);
            sum1 += __shfl_xor_sync(0xffffffffu, sum1, 2);

            l0 = l0 * sc0 + sum0;  l1 = l1 * sc1 + sum1;
            ml0 = mx0;             ml1 = mx1;

#pragma unroll
            for (int nf = 0; nf < 8; nf++) {
                o[nf][0] *= sc0; o[nf][1] *= sc0;
                o[nf][2] *= sc1; o[nf][3] *= sc1;
            }

            // ---- store P (tf32) to warp-private rows of Ps ----
#pragma unroll
            for (int nf = 0; nf < 8; nf++) {
                int cc = nf * 8 + 2 * tig;
                Ps[mrow * AST + cc]           = f2tf32(s[nf][0]);
                Ps[mrow * AST + cc + 1]       = f2tf32(s[nf][1]);
                Ps[(mrow + 8) * AST + cc]     = f2tf32(s[nf][2]);
                Ps[(mrow + 8) * AST + cc + 1] = f2tf32(s[nf][3]);
            }
            __syncwarp();

            // ---- O += P V ----
#pragma unroll
            for (int kf = 0; kf < 8; kf++) {
                unsigned pa0 = Ps[mrow * AST + kf * 8 + tig];
                unsigned pa1 = Ps[(mrow + 8) * AST + kf * 8 + tig];
                unsigned pa2 = Ps[mrow * AST + kf * 8 + tig + 4];
                unsigned pa3 = Ps[(mrow + 8) * AST + kf * 8 + tig + 4];
#pragma unroll
                for (int nf = 0; nf < 8; nf++) {
                    unsigned vb0 = Vs[(kf * 8 + tig) * VST + nf * 8 + gid];
                    unsigned vb1 = Vs[(kf * 8 + tig + 4) * VST + nf * 8 + gid];
                    mma_tf32(o[nf], pa0, pa1, pa2, pa3, vb0, vb1);
                }
            }
        }
        __syncthreads();
    }

    // ---- normalize + round + write attended [B*S, E] ----
    const float inv0 = 1.0f / l0, inv1 = 1.0f / l1;
#pragma unroll
    for (int nf = 0; nf < 8; nf++) {
        int col = h * HD + nf * 8 + 2 * tig;
        float2 v0 = make_float2(f2tf32f(o[nf][0] * inv0), f2tf32f(o[nf][1] * inv0));
        float2 v1 = make_float2(f2tf32f(o[nf][2] * inv1), f2tf32f(o[nf][3] * inv1));
        *(float2*)&g_Att[(size_t)(b * S_LEN + row0g) * E_DIM + col] = v0;
        *(float2*)&g_Att[(size_t)(b * S_LEN + row1g) * E_DIM + col] = v1;
    }
}

// ---------------------------------------------------------------------------
// Kernel 3: output projection. out[8192,768] = Att @ Wo + b_out.
// 3-stage cp.async pipeline, tf32 MMA. Dynamic smem.
// ---------------------------------------------------------------------------
__global__ __launch_bounds__(256) void out_gemm(
    const float* __restrict__ bias, float* __restrict__ out)
{
    extern __shared__ unsigned smg[];
    unsigned* Asb = smg;
    unsigned* Bsb = smg + 3 * GA_SZ;

    const int t    = threadIdx.x;
    const int lane = t & 31, warp = t >> 5;
    const int gid  = lane >> 2, tig = lane & 3;
    const int wm   = warp >> 2, wn = warp & 3;
    const int row0 = blockIdx.y * 128;
    const int col0 = blockIdx.x * 128;

    float acc[4][4][4] = {};

    auto stage = [&](int buf, int kk) {
        unsigned* A = Asb + buf * GA_SZ;
        unsigned* B = Bsb + buf * GB_SZ;
#pragma unroll
        for (int i = 0; i < 2; i++) {
            int c = t + i * 256;
            int rr = c >> 2, c4 = (c & 3) * 4;
            cp16(&A[rr * GA_ST + c4], &g_Att[(size_t)(row0 + rr) * E_DIM + kk + c4]);
        }
#pragma unroll
        for (int i = 0; i < 2; i++) {
            int c = t + i * 256;
            int rr = c >> 5, c4 = (c & 31) * 4;
            cp16(&B[rr * GB_ST + c4], &g_Wo[(size_t)(kk + rr) * E_DIM + col0 + c4]);
        }
        CP_COMMIT();
    };

    const int NT = E_DIM / 16;
    stage(0, 0);
    stage(1, 16);
    int buf = 0;
    for (int it = 0; it < NT; it++) {
        if (it + 2 < NT)      { stage((it + 2) % 3, (it + 2) * 16); CP_WAIT(2); }
        else if (it + 1 < NT) { CP_WAIT(1); }
        else                  { CP_WAIT(0); }
        __syncthreads();
        unsigned* A = Asb + buf * GA_SZ;
        unsigned* B = Bsb + buf * GB_SZ;
#pragma unroll
        for (int kf = 0; kf < 2; kf++) {
            unsigned a[4][4], b[4][2];
#pragma unroll
            for (int mf = 0; mf < 4; mf++) {
                int m = wm * 64 + mf * 16 + gid;
                a[mf][0] = A[m * GA_ST + kf * 8 + tig];
                a[mf][1] = A[(m + 8) * GA_ST + kf * 8 + tig];
                a[mf][2] = A[m * GA_ST + kf * 8 + tig + 4];
                a[mf][3] = A[(m + 8) * GA_ST + kf * 8 + tig + 4];
            }
#pragma unroll
            for (int nf = 0; nf < 4; nf++) {
                int n = wn * 32 + nf * 8 + gid;
                b[nf][0] = B[(kf * 8 + tig) * GB_ST + n];
                b[nf][1] = B[(kf * 8 + tig + 4) * GB_ST + n];
            }
#pragma unroll
            for (int mf = 0; mf < 4; mf++)
#pragma unroll
                for (int nf = 0; nf < 4; nf++)
                    mma_tf32(acc[mf][nf], a[mf][0], a[mf][1], a[mf][2], a[mf][3],
                             b[nf][0], b[nf][1]);
        }
        __syncthreads();
        buf = (buf + 1) % 3;
    }

#pragma unroll
    for (int nf = 0; nf < 4; nf++) {
        int c = col0 + wn * 32 + nf * 8 + 2 * tig;
        float b0v = bias[c], b1v = bias[c + 1];
#pragma unroll
        for (int mf = 0; mf < 4; mf++) {
#pragma unroll
            for (int rr = 0; rr < 2; rr++) {
                int m = row0 + wm * 64 + mf * 16 + gid + rr * 8;
                float2 vv;
                vv.x = acc[mf][nf][rr * 2]     + b0v;
                vv.y = acc[mf][nf][rr * 2 + 1] + b1v;
                *(float2*)&out[(size_t)m * E_DIM + c] = vv;
            }
        }
    }
}

// ---------------------------------------------------------------------------
extern "C" void kernel_launch(void* const* d_in, const int* in_sizes, int n_in,
                              void* d_out, int out_size)
{
    const float* x     = (const float*)d_in[0];
    const float* w_qkv = (const float*)d_in[1];
    const float* b_qkv = (const float*)d_in[2];
    const float* w_out = (const float*)d_in[3];
    const float* b_out = (const float*)d_in[4];
    float* out = (float*)d_out;

    cudaFuncSetAttribute(attn_kernel,
                         cudaFuncAttributeMaxDynamicSharedMemorySize, ATTN_SMEM);
    cudaFuncSetAttribute(qkv_gemm,
                         cudaFuncAttributeMaxDynamicSharedMemorySize, GEMM_SMEM);
    cudaFuncSetAttribute(out_gemm,
                         cudaFuncAttributeMaxDynamicSharedMemorySize, GEMM_SMEM);

    prepass<<<1024, 256>>>(x, w_qkv, w_out);

    dim3 g1(QKV_N / 128, NTOK / 128);     // (18, 64)
    qkv_gemm<<<g1, 256, GEMM_SMEM>>>(b_qkv);

    attn_kernel<<<NQB * NH * BATCH, 256, ATTN_SMEM>>>();   // 768, descending

    dim3 g3(E_DIM / 128, NTOK / 128);     // (6, 64)
    out_gemm<<<g3, 256, GEMM_SMEM>>>(b_out, out);
}